// round 1
// baseline (speedup 1.0000x reference)
#include <cuda_runtime.h>
#include <math.h>

#define DIM 512
#define TAU 0.1f
#define EPS_NORM 1e-12f
#define EPS_DENOM 1e-8f

__device__ float  g_av[DIM];
__device__ double g_neg_sum;
__device__ double g_pos_sum;

// ---------------------------------------------------------------------------
// Kernel 0: normalize anchor into g_av, zero accumulators. 512 threads.
// ---------------------------------------------------------------------------
__global__ void k_anchor(const float* __restrict__ anchor) {
    __shared__ float red[16];
    int tid = threadIdx.x;           // 0..511
    float x  = anchor[tid];
    float ss = x * x;
    #pragma unroll
    for (int o = 16; o > 0; o >>= 1) ss += __shfl_xor_sync(0xffffffffu, ss, o);
    if ((tid & 31) == 0) red[tid >> 5] = ss;
    __syncthreads();
    if (tid < 16) {
        float v = red[tid];
        #pragma unroll
        for (int o = 8; o > 0; o >>= 1) v += __shfl_xor_sync(0xffffu, v, o);
        if (tid == 0) red[0] = v;
    }
    __syncthreads();
    float inv = 1.0f / fmaxf(sqrtf(red[0]), EPS_NORM);
    g_av[tid] = x * inv;
    if (tid == 0) { g_neg_sum = 0.0; g_pos_sum = 0.0; }
}

// ---------------------------------------------------------------------------
// Kernel 1: stream hard negatives. One warp per row (512 floats = 4 float4
// per lane), compute dot(h, av) and ||h||^2 in one pass, exp(logit), reduce
// per block, one double atomicAdd per block.
// ---------------------------------------------------------------------------
template<int WARPS>
__global__ void k_neg(const float4* __restrict__ h, int nrows) {
    __shared__ float part[WARPS];
    const int warp = threadIdx.x >> 5;
    const int lane = threadIdx.x & 31;
    const int row  = blockIdx.x * WARPS + warp;

    float ex = 0.0f;
    if (row < nrows) {
        const float4* hr  = h + (size_t)row * (DIM / 4);
        const float4* av4 = (const float4*)g_av;
        float dot = 0.0f, ss = 0.0f;
        #pragma unroll
        for (int i = 0; i < 4; i++) {
            float4 v = hr[lane + 32 * i];
            float4 a = av4[lane + 32 * i];
            dot += v.x * a.x + v.y * a.y + v.z * a.z + v.w * a.w;
            ss  += v.x * v.x + v.y * v.y + v.z * v.z + v.w * v.w;
        }
        #pragma unroll
        for (int o = 16; o > 0; o >>= 1) {
            dot += __shfl_xor_sync(0xffffffffu, dot, o);
            ss  += __shfl_xor_sync(0xffffffffu, ss, o);
        }
        if (lane == 0) {
            float l = dot / (fmaxf(sqrtf(ss), EPS_NORM) * TAU);
            ex = expf(l);
        }
    }
    if (lane == 0) part[warp] = ex;
    __syncthreads();
    if (threadIdx.x == 0) {
        float s = 0.0f;
        #pragma unroll
        for (int i = 0; i < WARPS; i++) s += part[i];
        atomicAdd(&g_neg_sum, (double)s);
    }
}

// ---------------------------------------------------------------------------
// Kernel 2: synthesized negatives. Block j < n_mix -> "hardest" (anchor-mix),
// else "harder" (neg-neg mix). 128 threads, each owns one float4 of the row.
// Rows are L2-resident (already streamed by k_neg... actually launched after,
// but only ~192 rows => negligible traffic either way).
// ---------------------------------------------------------------------------
__device__ __forceinline__ float block_reduce_128(float v, float* sh) {
    #pragma unroll
    for (int o = 16; o > 0; o >>= 1) v += __shfl_xor_sync(0xffffffffu, v, o);
    if ((threadIdx.x & 31) == 0) sh[threadIdx.x >> 5] = v;
    __syncthreads();
    float r = sh[0] + sh[1] + sh[2] + sh[3];
    __syncthreads();
    return r;
}

__global__ void k_mix(const float* __restrict__ h,
                      const int* __restrict__ mix_idx,
                      const int* __restrict__ idx_a,
                      const int* __restrict__ idx_b,
                      const float* __restrict__ alpha_raw,
                      const float* __restrict__ beta_raw,
                      int n_mix) {
    __shared__ float sh[4];
    const int tid = threadIdx.x;   // 0..127
    const int j   = blockIdx.x;

    const float4* av4 = (const float4*)g_av;
    float4 a = av4[tid];

    float4 v;
    if (j < n_mix) {
        // hardest = l2norm((1-alpha) * h_norm[m] + alpha * a_norm)
        int   m     = mix_idx[j];
        float alpha = alpha_raw[j] * 0.4f + 0.1f;
        const float4* hr = (const float4*)(h + (size_t)m * DIM);
        float4 x = hr[tid];
        float ssx = x.x * x.x + x.y * x.y + x.z * x.z + x.w * x.w;
        ssx = block_reduce_128(ssx, sh);
        float inv = (1.0f - alpha) / fmaxf(sqrtf(ssx), EPS_NORM);
        v.x = x.x * inv + alpha * a.x;
        v.y = x.y * inv + alpha * a.y;
        v.z = x.z * inv + alpha * a.z;
        v.w = x.w * inv + alpha * a.w;
    } else {
        // harder = l2norm(beta * h_norm[ia] + (1-beta) * h_norm[ib])
        int   jj   = j - n_mix;
        int   ia   = idx_a[jj];
        int   ib   = idx_b[jj];
        float beta = beta_raw[jj] * 0.4f + 0.3f;
        const float4* ra = (const float4*)(h + (size_t)ia * DIM);
        const float4* rb = (const float4*)(h + (size_t)ib * DIM);
        float4 xa = ra[tid];
        float4 xb = rb[tid];
        float ssa = xa.x * xa.x + xa.y * xa.y + xa.z * xa.z + xa.w * xa.w;
        float ssb = xb.x * xb.x + xb.y * xb.y + xb.z * xb.z + xb.w * xb.w;
        ssa = block_reduce_128(ssa, sh);
        ssb = block_reduce_128(ssb, sh);
        float inva = beta          / fmaxf(sqrtf(ssa), EPS_NORM);
        float invb = (1.0f - beta) / fmaxf(sqrtf(ssb), EPS_NORM);
        v.x = xa.x * inva + xb.x * invb;
        v.y = xa.y * inva + xb.y * invb;
        v.z = xa.z * inva + xb.z * invb;
        v.w = xa.w * inva + xb.w * invb;
    }

    float ssv = v.x * v.x + v.y * v.y + v.z * v.z + v.w * v.w;
    float dv  = v.x * a.x + v.y * a.y + v.z * a.z + v.w * a.w;
    ssv = block_reduce_128(ssv, sh);
    dv  = block_reduce_128(dv, sh);

    if (tid == 0) {
        float l = dv / (fmaxf(sqrtf(ssv), EPS_NORM) * TAU);
        atomicAdd(&g_neg_sum, (double)expf(l));
    }
}

// ---------------------------------------------------------------------------
// Kernel 3: positives. Same streaming shape; consumes g_neg_sum (previous
// kernels in the stream have completed). term = log1p((S+eps) * exp(-l)).
// ---------------------------------------------------------------------------
template<int WARPS>
__global__ void k_pos(const float4* __restrict__ p, int nrows) {
    __shared__ float part[WARPS];
    const int warp = threadIdx.x >> 5;
    const int lane = threadIdx.x & 31;
    const int row  = blockIdx.x * WARPS + warp;

    float term = 0.0f;
    if (row < nrows) {
        const float4* pr  = p + (size_t)row * (DIM / 4);
        const float4* av4 = (const float4*)g_av;
        float dot = 0.0f, ss = 0.0f;
        #pragma unroll
        for (int i = 0; i < 4; i++) {
            float4 v = pr[lane + 32 * i];
            float4 a = av4[lane + 32 * i];
            dot += v.x * a.x + v.y * a.y + v.z * a.z + v.w * a.w;
            ss  += v.x * v.x + v.y * v.y + v.z * v.z + v.w * v.w;
        }
        #pragma unroll
        for (int o = 16; o > 0; o >>= 1) {
            dot += __shfl_xor_sync(0xffffffffu, dot, o);
            ss  += __shfl_xor_sync(0xffffffffu, ss, o);
        }
        if (lane == 0) {
            float l = dot / (fmaxf(sqrtf(ss), EPS_NORM) * TAU);
            float S = (float)g_neg_sum + EPS_DENOM;
            term = log1pf(S * expf(-l));
        }
    }
    if (lane == 0) part[warp] = term;
    __syncthreads();
    if (threadIdx.x == 0) {
        float s = 0.0f;
        #pragma unroll
        for (int i = 0; i < WARPS; i++) s += part[i];
        atomicAdd(&g_pos_sum, (double)s);
    }
}

// ---------------------------------------------------------------------------
// Kernel 4: finalize.
// ---------------------------------------------------------------------------
__global__ void k_final(float* __restrict__ out, double inv_npos) {
    out[0] = (float)(g_pos_sum * inv_npos);
}

extern "C" void kernel_launch(void* const* d_in, const int* in_sizes, int n_in,
                              void* d_out, int out_size) {
    const float* anchor    = (const float*)d_in[0];
    const float* positives = (const float*)d_in[1];
    const float* hardnegs  = (const float*)d_in[2];
    const int*   mix_idx   = (const int*)d_in[3];
    const int*   idx_a     = (const int*)d_in[4];
    const int*   idx_b     = (const int*)d_in[5];
    const float* alpha_raw = (const float*)d_in[6];
    const float* beta_raw  = (const float*)d_in[7];

    const int n_pos  = in_sizes[1] / DIM;
    const int n_hard = in_sizes[2] / DIM;
    const int n_mix  = in_sizes[3];

    constexpr int WARPS = 8;

    k_anchor<<<1, DIM>>>(anchor);
    k_neg<WARPS><<<(n_hard + WARPS - 1) / WARPS, WARPS * 32>>>(
        (const float4*)hardnegs, n_hard);
    k_mix<<<2 * n_mix, 128>>>(hardnegs, mix_idx, idx_a, idx_b,
                              alpha_raw, beta_raw, n_mix);
    k_pos<WARPS><<<(n_pos + WARPS - 1) / WARPS, WARPS * 32>>>(
        (const float4*)positives, n_pos);
    k_final<<<1, 1>>>((float*)d_out, 1.0 / (double)n_pos);
}

// round 2
// speedup vs baseline: 1.0539x; 1.0539x over previous
#include <cuda_runtime.h>
#include <math.h>

#define DIM 512
#define NF4 (DIM / 4)
#define TAU 0.1f
#define EPS_NORM 1e-12f
#define EPS_DENOM 1e-8f
#define MAX_POS 32768

__device__ float  g_av[DIM];
__device__ double g_neg_sum;
__device__ float  g_pos_logit[MAX_POS];

// ---------------------------------------------------------------------------
// Kernel 0: normalize anchor into g_av, zero accumulator. 512 threads.
// ---------------------------------------------------------------------------
__global__ void k_anchor(const float* __restrict__ anchor) {
    __shared__ float red[16];
    int tid = threadIdx.x;           // 0..511
    float x  = anchor[tid];
    float ss = x * x;
    #pragma unroll
    for (int o = 16; o > 0; o >>= 1) ss += __shfl_xor_sync(0xffffffffu, ss, o);
    if ((tid & 31) == 0) red[tid >> 5] = ss;
    __syncthreads();
    if (tid < 16) {
        float v = red[tid];
        #pragma unroll
        for (int o = 8; o > 0; o >>= 1) v += __shfl_xor_sync(0xffffu, v, o);
        if (tid == 0) red[0] = v;
    }
    __syncthreads();
    float inv = 1.0f / fmaxf(sqrtf(red[0]), EPS_NORM);
    g_av[tid] = x * inv;
    if (tid == 0) g_neg_sum = 0.0;
}

// ---------------------------------------------------------------------------
// Fused streaming kernel. Grid = [neg blocks | pos blocks | mix blocks].
// 256 threads / block, WARPS=8 rows per block for the streaming paths.
//   neg block: per-row exp(dot/(||h||*tau)) -> block sum -> atomicAdd(g_neg_sum)
//   pos block: per-row logit -> g_pos_logit[row]   (no dependency on S)
//   mix block: synthesized negative -> atomicAdd(g_neg_sum)
// ---------------------------------------------------------------------------
template<int WARPS>
__global__ void __launch_bounds__(WARPS * 32) k_fused(
    const float4* __restrict__ h,
    const float4* __restrict__ p,
    const int*    __restrict__ mix_idx,
    const int*    __restrict__ idx_a,
    const int*    __restrict__ idx_b,
    const float*  __restrict__ alpha_raw,
    const float*  __restrict__ beta_raw,
    int nb_neg, int nb_pos,
    int n_hard, int n_pos, int n_mix)
{
    __shared__ float4 sav[NF4];     // anchor broadcast (2 KB)
    __shared__ float  part[WARPS];

    const int tid  = threadIdx.x;
    const int warp = tid >> 5;
    const int lane = tid & 31;

    // broadcast normalized anchor into shared
    {
        const float4* av4 = (const float4*)g_av;
        for (int i = tid; i < NF4; i += WARPS * 32) sav[i] = av4[i];
    }
    __syncthreads();

    const int b = blockIdx.x;

    if (b < nb_neg + nb_pos) {
        // ----- streaming path (negatives or positives) -----
        const bool    is_neg = (b < nb_neg);
        const int     bb     = is_neg ? b : b - nb_neg;
        const int     nrows  = is_neg ? n_hard : n_pos;
        const float4* base   = is_neg ? h : p;
        const int     row    = bb * WARPS + warp;

        float val = 0.0f;   // exp(logit) for neg path; unused for pos
        if (row < nrows) {
            const float4* r = base + (size_t)row * NF4;
            float dot = 0.0f, ss = 0.0f;
            #pragma unroll
            for (int i = 0; i < 4; i++) {
                float4 v = r[lane + 32 * i];
                float4 a = sav[lane + 32 * i];
                dot += v.x * a.x + v.y * a.y + v.z * a.z + v.w * a.w;
                ss  += v.x * v.x + v.y * v.y + v.z * v.z + v.w * v.w;
            }
            #pragma unroll
            for (int o = 16; o > 0; o >>= 1) {
                dot += __shfl_xor_sync(0xffffffffu, dot, o);
                ss  += __shfl_xor_sync(0xffffffffu, ss, o);
            }
            if (lane == 0) {
                float l = dot / (fmaxf(sqrtf(ss), EPS_NORM) * TAU);
                if (is_neg) val = expf(l);
                else        g_pos_logit[row] = l;
            }
        }
        if (!is_neg) return;

        if (lane == 0) part[warp] = val;
        __syncthreads();
        if (tid == 0) {
            float s = 0.0f;
            #pragma unroll
            for (int i = 0; i < WARPS; i++) s += part[i];
            atomicAdd(&g_neg_sum, (double)s);
        }
        return;
    }

    // ----- mix path: one synthesized negative per block -----
    const int j = b - (nb_neg + nb_pos);          // 0 .. 2*n_mix-1
    const float* hs = (const float*)h;

    // all 256 threads participate in reductions; first 128 own data
    const bool active = (tid < NF4);
    float4 a = active ? sav[tid] : make_float4(0.f, 0.f, 0.f, 0.f);

    float4 v = make_float4(0.f, 0.f, 0.f, 0.f);

    auto block_reduce = [&](float x) -> float {
        #pragma unroll
        for (int o = 16; o > 0; o >>= 1) x += __shfl_xor_sync(0xffffffffu, x, o);
        if (lane == 0) part[warp] = x;
        __syncthreads();
        float r = 0.0f;
        #pragma unroll
        for (int i = 0; i < WARPS; i++) r += part[i];
        __syncthreads();
        return r;
    };

    if (j < n_mix) {
        // hardest = l2norm((1-alpha) * h_norm[m] + alpha * a_norm)
        int   m     = mix_idx[j];
        float alpha = alpha_raw[j] * 0.4f + 0.1f;
        float4 x = make_float4(0.f, 0.f, 0.f, 0.f);
        if (active) x = ((const float4*)(hs + (size_t)m * DIM))[tid];
        float ssx = block_reduce(x.x * x.x + x.y * x.y + x.z * x.z + x.w * x.w);
        float inv = (1.0f - alpha) / fmaxf(sqrtf(ssx), EPS_NORM);
        v.x = x.x * inv + alpha * a.x;
        v.y = x.y * inv + alpha * a.y;
        v.z = x.z * inv + alpha * a.z;
        v.w = x.w * inv + alpha * a.w;
    } else {
        // harder = l2norm(beta * h_norm[ia] + (1-beta) * h_norm[ib])
        int   jj   = j - n_mix;
        int   ia   = idx_a[jj];
        int   ib   = idx_b[jj];
        float beta = beta_raw[jj] * 0.4f + 0.3f;
        float4 xa = make_float4(0.f, 0.f, 0.f, 0.f);
        float4 xb = make_float4(0.f, 0.f, 0.f, 0.f);
        if (active) {
            xa = ((const float4*)(hs + (size_t)ia * DIM))[tid];
            xb = ((const float4*)(hs + (size_t)ib * DIM))[tid];
        }
        float ssa = block_reduce(xa.x * xa.x + xa.y * xa.y + xa.z * xa.z + xa.w * xa.w);
        float ssb = block_reduce(xb.x * xb.x + xb.y * xb.y + xb.z * xb.z + xb.w * xb.w);
        float inva = beta          / fmaxf(sqrtf(ssa), EPS_NORM);
        float invb = (1.0f - beta) / fmaxf(sqrtf(ssb), EPS_NORM);
        v.x = xa.x * inva + xb.x * invb;
        v.y = xa.y * inva + xb.y * invb;
        v.z = xa.z * inva + xb.z * invb;
        v.w = xa.w * inva + xb.w * invb;
    }

    float ssv = block_reduce(v.x * v.x + v.y * v.y + v.z * v.z + v.w * v.w);
    float dv  = block_reduce(v.x * a.x + v.y * a.y + v.z * a.z + v.w * a.w);

    if (tid == 0) {
        float l = dv / (fmaxf(sqrtf(ssv), EPS_NORM) * TAU);
        atomicAdd(&g_neg_sum, (double)expf(l));
    }
}

// ---------------------------------------------------------------------------
// Finalize: loss = mean_i log1p((S + eps) * exp(-l_i)). One block.
// ---------------------------------------------------------------------------
__global__ void k_final(float* __restrict__ out, int n_pos) {
    __shared__ double red[32];
    const int tid = threadIdx.x;          // 1024 threads
    const float S = (float)g_neg_sum + EPS_DENOM;

    double acc = 0.0;
    for (int i = tid; i < n_pos; i += blockDim.x) {
        float l = g_pos_logit[i];
        acc += (double)log1pf(S * expf(-l));
    }
    #pragma unroll
    for (int o = 16; o > 0; o >>= 1)
        acc += __shfl_xor_sync(0xffffffffu, acc, o);
    if ((tid & 31) == 0) red[tid >> 5] = acc;
    __syncthreads();
    if (tid < 32) {
        double v = (tid < (blockDim.x >> 5)) ? red[tid] : 0.0;
        #pragma unroll
        for (int o = 16; o > 0; o >>= 1)
            v += __shfl_xor_sync(0xffffffffu, v, o);
        if (tid == 0) out[0] = (float)(v / (double)n_pos);
    }
}

extern "C" void kernel_launch(void* const* d_in, const int* in_sizes, int n_in,
                              void* d_out, int out_size) {
    const float* anchor    = (const float*)d_in[0];
    const float* positives = (const float*)d_in[1];
    const float* hardnegs  = (const float*)d_in[2];
    const int*   mix_idx   = (const int*)d_in[3];
    const int*   idx_a     = (const int*)d_in[4];
    const int*   idx_b     = (const int*)d_in[5];
    const float* alpha_raw = (const float*)d_in[6];
    const float* beta_raw  = (const float*)d_in[7];

    const int n_pos  = in_sizes[1] / DIM;
    const int n_hard = in_sizes[2] / DIM;
    const int n_mix  = in_sizes[3];

    constexpr int WARPS = 8;
    const int nb_neg = (n_hard + WARPS - 1) / WARPS;
    const int nb_pos = (n_pos  + WARPS - 1) / WARPS;
    const int grid   = nb_neg + nb_pos + 2 * n_mix;

    k_anchor<<<1, DIM>>>(anchor);
    k_fused<WARPS><<<grid, WARPS * 32>>>(
        (const float4*)hardnegs, (const float4*)positives,
        mix_idx, idx_a, idx_b, alpha_raw, beta_raw,
        nb_neg, nb_pos, n_hard, n_pos, n_mix);
    k_final<<<1, 1024>>>((float*)d_out, n_pos);
}